// round 9
// baseline (speedup 1.0000x reference)
#include <cuda_runtime.h>
#include <cuda_fp16.h>
#include <math.h>
#include <stdint.h>

#define NPTS      524288
#define GRIDSZ    512
#define NC        36
#define KIN       129
#define K1PAD     136
#define HID       256
#define NOUT      129
#define TB        128
#define NTHREADS  512
#define NTILES    (NPTS/TB)        // 4096
#define GRID_CTAS 592

// ---- smem byte layout (weights resident for CTA lifetime) ----
// W1 [0,69632) ; W2 [69632,154112) ; A2 [154112,221696) (A1 aliased at same base)
// b1 f32 [221696,222720) ; b2 f32 [222720,223360)
#define BY_W1   0
#define BY_W2   69632
#define BY_A2   154112
#define BY_A1   154112
#define BY_B1S  221696
#define BY_B2S  222720
#define SMEM_BYTES 223360

#define SA1_W 68          // A1 row stride in 32-bit words (136 halfs); 68%32=4 -> conflict-free
#define SW1_W 68          // W1 row stride (n-major)
#define SA2_W 132         // A2 row stride (264 halfs); 132%32=4 -> conflict-free
#define SW2_W 132         // W2 row stride

__device__ float g_planesT[3*GRIDSZ*GRIDSZ*NC];   // [i][y][x][c]
__device__ float g_linesT[3*GRIDSZ*NC];           // [i][l][c]
__device__ __align__(16) __half g_W1h[256*136];   // [n][k], fp16, zero-padded k>=129
__device__ __align__(16) __half g_W2h[160*264];   // [n][k], fp16, zero-padded n>=129 / k>=256

// ================= prep kernels =================
__global__ void __launch_bounds__(256) transpose_planes(const float* __restrict__ planes) {
    __shared__ float tile[8][32*37];
    int wid = threadIdx.x >> 5, lane = threadIdx.x & 31;
    int cell0 = (blockIdx.x * 8 + wid) * 32;
    int i = cell0 / (GRIDSZ*GRIDSZ);
    int rem = cell0 - i*GRIDSZ*GRIDSZ;
    int y = rem >> 9, x0 = rem & (GRIDSZ-1);
    const float* src = planes + (long)i*NC*GRIDSZ*GRIDSZ + (long)y*GRIDSZ + x0 + lane;
    float* t = tile[wid];
    #pragma unroll
    for (int c = 0; c < NC; c++) t[lane*37 + c] = src[(long)c*GRIDSZ*GRIDSZ];
    __syncwarp();
    float* dst = g_planesT + (long)cell0 * NC;
    #pragma unroll
    for (int k = 0; k < 9; k++) {
        int fo = (k*32 + lane) * 4;
        int cc = fo / NC, c = fo - cc*NC;
        *(float4*)(dst + fo) = make_float4(t[cc*37+c], t[cc*37+c+1], t[cc*37+c+2], t[cc*37+c+3]);
    }
}

__global__ void transpose_lines(const float* __restrict__ lines) {
    int t2 = blockIdx.x * blockDim.x + threadIdx.x;
    if (t2 < 3*GRIDSZ) {
        int j = t2 & (GRIDSZ-1), i = t2 >> 9;
        float* dst = g_linesT + t2*NC;
        const float* src = lines + (long)i*NC*GRIDSZ + j;
        #pragma unroll
        for (int c = 0; c < NC; c++) dst[c] = src[(long)c*GRIDSZ];
    }
}

__global__ void pack_weights_kernel(const float* __restrict__ W1, const float* __restrict__ W2) {
    int idx = blockIdx.x * blockDim.x + threadIdx.x;
    const int T1 = 256*136;          // 34816
    const int T2 = 160*264;          // 42240
    if (idx < T1) {
        int n = idx / 136, k = idx - n*136;
        g_W1h[idx] = (k < KIN) ? __float2half_rn(W1[k*HID + n]) : __float2half_rn(0.f);
    } else if (idx < T1 + T2) {
        int j = idx - T1;
        int n = j / 264, k = j - n*264;
        float v = (k < 256 && n < NOUT) ? W2[k*NOUT + n] : 0.f;
        g_W2h[j] = __float2half_rn(v);
    }
}

// ================= mma helpers =================
__device__ __forceinline__ void mma_f16_k16(float c[4], unsigned a0, unsigned a1,
                                            unsigned a2, unsigned a3,
                                            unsigned b0, unsigned b1) {
    asm volatile(
        "mma.sync.aligned.m16n8k16.row.col.f32.f16.f16.f32 "
        "{%0,%1,%2,%3},{%4,%5,%6,%7},{%8,%9},{%0,%1,%2,%3};"
        : "+f"(c[0]), "+f"(c[1]), "+f"(c[2]), "+f"(c[3])
        : "r"(a0), "r"(a1), "r"(a2), "r"(a3), "r"(b0), "r"(b1));
}
__device__ __forceinline__ void mma_f16_k8(float c[4], unsigned a0, unsigned a1, unsigned b0) {
    asm volatile(
        "mma.sync.aligned.m16n8k8.row.col.f32.f16.f16.f32 "
        "{%0,%1,%2,%3},{%4,%5},{%6},{%0,%1,%2,%3};"
        : "+f"(c[0]), "+f"(c[1]), "+f"(c[2]), "+f"(c[3])
        : "r"(a0), "r"(a1), "r"(b0));
}

__device__ __forceinline__ float softplus100(float z) {
    float y = 100.f * z;
    return 0.01f * (fmaxf(y, 0.f) + __logf(1.f + __expf(-fabsf(y))));
}
__device__ __forceinline__ void cp16(uint32_t dst, const void* src) {
    asm volatile("cp.async.cg.shared.global [%0], [%1], 16;" :: "r"(dst), "l"(src));
}
__device__ __forceinline__ void cp_commit() { asm volatile("cp.async.commit_group;"); }
__device__ __forceinline__ void cp_wait0()  { asm volatile("cp.async.wait_group 0;" ::: "memory"); }

// ================= main fused kernel (persistent weights) =================
__global__ void __launch_bounds__(NTHREADS, 1)
tensosdf_main(const float* __restrict__ xyz,
              const float* __restrict__ b1, const float* __restrict__ b2,
              float* __restrict__ out) {
    extern __shared__ char smem[];
    const uint32_t smem_u32 = (uint32_t)__cvta_generic_to_shared(smem);
    float* b1s = (float*)(smem + BY_B1S);
    float* b2s = (float*)(smem + BY_B2S);

    const int tid  = threadIdx.x;
    const int lane = tid & 31;
    const int warp = tid >> 5;
    const int g = lane >> 2;
    const int t = lane & 3;

    // ---- biases (once per CTA) ----
    if (tid < HID) b1s[tid] = b1[tid];
    else if (tid < HID + 160) { int c = tid - HID; b2s[c] = (c < NOUT) ? b2[c] : 0.f; }

    // ---- stage BOTH weight images once (async; overlaps first gather) ----
    // W1: 4352 x 16B ; W2: 5280 x 16B
    for (int idx = tid; idx < 4352 + 5280; idx += NTHREADS) {
        if (idx < 4352)
            cp16(smem_u32 + BY_W1 + (uint32_t)idx*16u, (const char*)g_W1h + idx*16);
        else {
            int j = idx - 4352;
            cp16(smem_u32 + BY_W2 + (uint32_t)j*16u, (const char*)g_W2h + j*16);
        }
    }
    cp_commit();
    bool first = true;

    // gather lane constants
    const unsigned FULL = 0xffffffffu;
    const int i_of = (lane < 9) ? 0 : ((lane < 18) ? 1 : 2);
    const int cj = (lane - i_of*9) * 4;
    const bool act = lane < 27;
    const int fcol = i_of*NC + cj;
    const int pcol = 108 + lane;

    const int mt = warp & 3;          // m-tile: 32 rows
    const int nq = warp >> 2;         // 0..3
    const int arow = mt * 32;

    const uint32_t* Aw  = (const uint32_t*)(smem + BY_A1);
    const uint32_t* Bw  = (const uint32_t*)(smem + BY_W1);
    const uint32_t* Aw2 = (const uint32_t*)(smem + BY_A2);
    const uint32_t* Bw2 = (const uint32_t*)(smem + BY_W2);

    for (int tile = blockIdx.x; tile < NTILES; tile += GRID_CTAS) {
        const int pbase = tile * TB;

        // ---- gather: warp handles 8 points -> fp16 A1 (stride 272B) ----
        {
            float vload = 0.f;
            int base3 = (pbase + warp*8)*3;
            if (lane < 24) vload = xyz[base3 + lane];

            #pragma unroll
            for (int pi = 0; pi < 8; pi++) {
                float x0 = __shfl_sync(FULL, vload, pi*3+0);
                float x1 = __shfl_sync(FULL, vload, pi*3+1);
                float x2 = __shfl_sync(FULL, vload, pi*3+2);
                float xn0 = 2.f*x0 - 1.f, xn1 = 2.f*x1 - 1.f, xn2 = 2.f*x2 - 1.f;
                int row = warp*8 + pi;
                char* rbase = smem + BY_A1 + row*272;

                if (act) {
                    float gx = (i_of == 2) ? xn1 : xn0;
                    float gy = (i_of == 0) ? xn1 : xn2;
                    float gl = (i_of == 0) ? xn2 : ((i_of == 1) ? xn1 : xn0);
                    float px = (gx + 1.f) * 0.5f * 511.f;
                    float py = (gy + 1.f) * 0.5f * 511.f;
                    float pl = (gl + 1.f) * 0.5f * 511.f;
                    int ix = min(max((int)floorf(px), 0), 510);
                    int iy = min(max((int)floorf(py), 0), 510);
                    int il = min(max((int)floorf(pl), 0), 510);
                    float wx = px - ix, wy = py - iy, wl = pl - il;
                    const float* pb = g_planesT + (((i_of*GRIDSZ + iy)*GRIDSZ) + ix)*NC + cj;
                    const float* lb = g_linesT + (i_of*GRIDSZ + il)*NC + cj;
                    float4 f00 = *(const float4*)pb;
                    float4 f01 = *(const float4*)(pb + NC);
                    float4 f10 = *(const float4*)(pb + GRIDSZ*NC);
                    float4 f11 = *(const float4*)(pb + GRIDSZ*NC + NC);
                    float4 l0  = *(const float4*)lb;
                    float4 l1  = *(const float4*)(lb + NC);
                    float rx, ry, rz, rw;
                    float fx0 = f00.x + wx*(f01.x - f00.x), fx1 = f10.x + wx*(f11.x - f10.x);
                    rx = (fx0 + wy*(fx1 - fx0)) * (l0.x + wl*(l1.x - l0.x));
                    fx0 = f00.y + wx*(f01.y - f00.y); fx1 = f10.y + wx*(f11.y - f10.y);
                    ry = (fx0 + wy*(fx1 - fx0)) * (l0.y + wl*(l1.y - l0.y));
                    fx0 = f00.z + wx*(f01.z - f00.z); fx1 = f10.z + wx*(f11.z - f10.z);
                    rz = (fx0 + wy*(fx1 - fx0)) * (l0.z + wl*(l1.z - l0.z));
                    fx0 = f00.w + wx*(f01.w - f00.w); fx1 = f10.w + wx*(f11.w - f10.w);
                    rw = (fx0 + wy*(fx1 - fx0)) * (l0.w + wl*(l1.w - l0.w));
                    *(__half2*)(rbase + fcol*2)     = __float22half2_rn(make_float2(rx, ry));
                    *(__half2*)(rbase + fcol*2 + 4) = __float22half2_rn(make_float2(rz, rw));
                }

                float pv;
                if (lane < 3) pv = (lane == 0) ? xn0 : ((lane == 1) ? xn1 : xn2);
                else if (lane < 21) {
                    int j = lane - 3, f = j / 6, rr = j - 6*f, d = rr % 3;
                    float xv = ((d == 0) ? xn0 : ((d == 1) ? xn1 : xn2)) * (float)(1 << f);
                    pv = (rr < 3) ? __sinf(xv) : __cosf(xv);
                } else pv = 0.f;
                if (pcol < K1PAD)
                    *(__half*)(rbase + pcol*2) = __float2half_rn(pv);
            }
        }

        if (first) { cp_wait0(); first = false; }
        __syncthreads();

        // ================= GEMM1: 16 warps = 4m(32) x 4n(64) =================
        float acc[2][8][4];
        #pragma unroll
        for (int i = 0; i < 2; i++)
            #pragma unroll
            for (int j = 0; j < 8; j++)
                #pragma unroll
                for (int q = 0; q < 4; q++) acc[i][j][q] = 0.f;

        #pragma unroll
        for (int ks = 0; ks < 8; ks++) {
            const uint32_t* A0 = Aw + (arow + g)*SA1_W + ks*8 + t;
            unsigned a00 = A0[0], a02 = A0[4];
            unsigned a01 = A0[8*SA1_W], a03 = A0[8*SA1_W + 4];
            const uint32_t* A1p = A0 + 16*SA1_W;
            unsigned a10 = A1p[0], a12 = A1p[4];
            unsigned a11 = A1p[8*SA1_W], a13 = A1p[8*SA1_W + 4];
            const uint32_t* B0 = Bw + (nq*64 + g)*SW1_W + ks*8 + t;
            #pragma unroll
            for (int nf = 0; nf < 8; nf++) {
                unsigned bb0 = B0[nf*8*SW1_W];
                unsigned bb1 = B0[nf*8*SW1_W + 4];
                mma_f16_k16(acc[0][nf], a00, a01, a02, a03, bb0, bb1);
                mma_f16_k16(acc[1][nf], a10, a11, a12, a13, bb0, bb1);
            }
        }
        {   // k8 tail: k = 128..135
            const uint32_t* A0 = Aw + (arow + g)*SA1_W + 64 + t;
            unsigned a00 = A0[0], a01 = A0[8*SA1_W];
            unsigned a10 = A0[16*SA1_W], a11 = A0[24*SA1_W];
            const uint32_t* B0 = Bw + (nq*64 + g)*SW1_W + 64 + t;
            #pragma unroll
            for (int nf = 0; nf < 8; nf++) {
                unsigned bb0 = B0[nf*8*SW1_W];
                mma_f16_k8(acc[0][nf], a00, a01, bb0);
                mma_f16_k8(acc[1][nf], a10, a11, bb0);
            }
        }

        __syncthreads();   // A1 reads done (A2 aliases A1 region)

        // epilogue 1: bias + softplus -> fp16 A2 (stride 528B)
        #pragma unroll
        for (int mf = 0; mf < 2; mf++) {
            #pragma unroll
            for (int nf = 0; nf < 8; nf++) {
                int col = nq*64 + nf*8 + 2*t;
                float bb0 = b1s[col], bb1 = b1s[col+1];
                int row0 = arow + mf*16 + g;
                float r0 = softplus100(acc[mf][nf][0] + bb0);
                float r1 = softplus100(acc[mf][nf][1] + bb1);
                float r2 = softplus100(acc[mf][nf][2] + bb0);
                float r3 = softplus100(acc[mf][nf][3] + bb1);
                *(__half2*)(smem + BY_A2 + row0*528 + col*2)     = __float22half2_rn(make_float2(r0, r1));
                *(__half2*)(smem + BY_A2 + (row0+8)*528 + col*2) = __float22half2_rn(make_float2(r2, r3));
            }
        }

        __syncthreads();

        // ================= GEMM2: 16 warps = 4m(32) x 4n(40) =================
        float acc2[2][5][4];
        #pragma unroll
        for (int i = 0; i < 2; i++)
            #pragma unroll
            for (int j = 0; j < 5; j++)
                #pragma unroll
                for (int q = 0; q < 4; q++) acc2[i][j][q] = 0.f;

        #pragma unroll
        for (int ks = 0; ks < 16; ks++) {
            const uint32_t* A0 = Aw2 + (arow + g)*SA2_W + ks*8 + t;
            unsigned a00 = A0[0], a02 = A0[4];
            unsigned a01 = A0[8*SA2_W], a03 = A0[8*SA2_W + 4];
            const uint32_t* A1p = A0 + 16*SA2_W;
            unsigned a10 = A1p[0], a12 = A1p[4];
            unsigned a11 = A1p[8*SA2_W], a13 = A1p[8*SA2_W + 4];
            const uint32_t* B0 = Bw2 + (nq*40 + g)*SW2_W + ks*8 + t;
            #pragma unroll
            for (int nf = 0; nf < 5; nf++) {
                unsigned bb0 = B0[nf*8*SW2_W];
                unsigned bb1 = B0[nf*8*SW2_W + 4];
                mma_f16_k16(acc2[0][nf], a00, a01, a02, a03, bb0, bb1);
                mma_f16_k16(acc2[1][nf], a10, a11, a12, a13, bb0, bb1);
            }
        }

        // epilogue 2: bias + store
        #pragma unroll
        for (int mf = 0; mf < 2; mf++) {
            #pragma unroll
            for (int nf = 0; nf < 5; nf++) {
                int col = nq*40 + nf*8 + 2*t;
                float o0 = acc2[mf][nf][0] + b2s[col];
                float o1 = acc2[mf][nf][1] + b2s[col+1];
                float o2 = acc2[mf][nf][2] + b2s[col];
                float o3 = acc2[mf][nf][3] + b2s[col+1];
                int r0 = (pbase + arow + mf*16 + g) * NOUT;
                int r1 = r0 + 8*NOUT;
                if (col < NOUT)     { out[r0 + col]     = o0; out[r1 + col]     = o2; }
                if (col + 1 < NOUT) { out[r0 + col + 1] = o1; out[r1 + col + 1] = o3; }
            }
        }

        __syncthreads();   // A2 reads done before next tile's gather overwrites A1 region
    }
}

extern "C" void kernel_launch(void* const* d_in, const int* in_sizes, int n_in,
                              void* d_out, int out_size) {
    const float* xyz    = (const float*)d_in[0];
    const float* planes = (const float*)d_in[1];
    const float* lines  = (const float*)d_in[2];
    const float* W1     = (const float*)d_in[3];
    const float* b1     = (const float*)d_in[4];
    const float* W2     = (const float*)d_in[5];
    const float* b2     = (const float*)d_in[6];
    float* out = (float*)d_out;

    static bool attr_set = false;
    if (!attr_set) {
        cudaFuncSetAttribute(tensosdf_main,
                             cudaFuncAttributeMaxDynamicSharedMemorySize, SMEM_BYTES);
        attr_set = true;
    }

    transpose_planes<<<3072, 256>>>(planes);
    transpose_lines<<<6, 256>>>(lines);
    const int npack = 256*136 + 160*264;
    pack_weights_kernel<<<(npack + 255) / 256, 256>>>(W1, W2);
    tensosdf_main<<<GRID_CTAS, NTHREADS, SMEM_BYTES>>>(xyz, b1, b2, out);
}

// round 10
// speedup vs baseline: 1.1006x; 1.1006x over previous
#include <cuda_runtime.h>
#include <cuda_fp16.h>
#include <math.h>
#include <stdint.h>

#define NPTS      524288
#define GRIDSZ    512
#define NC        36
#define KIN       129
#define K1PAD     136
#define HID       256
#define NOUT      129
#define TB        128
#define NTHREADS  512

// ---- smem byte layout ----
// phase1: W1 [0,69632) ; A1 [69632,104448) ; A2 [104448,172032)
// phase2: W2 [0,84480)  (unioned with W1+A1 after GEMM1)
// biases: b1 f32 [172032,173056) ; b2 f32 [173056,173696)
#define BY_W1   0
#define BY_A1   69632
#define BY_A2   104448
#define BY_B1S  172032
#define BY_B2S  173056
#define SMEM_BYTES 173696

#define SA1_B 272         // A1/W1 row stride bytes (136 halfs); 272%128=16 -> ldsm conflict-free
#define SA2_B 528         // A2/W2 row stride bytes (264 halfs); 528%128=16 -> ldsm conflict-free

__device__ float g_planesT[3*GRIDSZ*GRIDSZ*NC];   // [i][y][x][c]
__device__ float g_linesT[3*GRIDSZ*NC];           // [i][l][c]
__device__ __align__(16) __half g_W1h[256*136];   // [n][k], fp16, zero-padded k>=129
__device__ __align__(16) __half g_W2h[160*264];   // [n][k], fp16, zero-padded n>=129 / k>=256

// ================= prep kernels =================
__global__ void __launch_bounds__(256) transpose_planes(const float* __restrict__ planes) {
    __shared__ float tile[8][32*37];
    int wid = threadIdx.x >> 5, lane = threadIdx.x & 31;
    int cell0 = (blockIdx.x * 8 + wid) * 32;
    int i = cell0 / (GRIDSZ*GRIDSZ);
    int rem = cell0 - i*GRIDSZ*GRIDSZ;
    int y = rem >> 9, x0 = rem & (GRIDSZ-1);
    const float* src = planes + (long)i*NC*GRIDSZ*GRIDSZ + (long)y*GRIDSZ + x0 + lane;
    float* t = tile[wid];
    #pragma unroll
    for (int c = 0; c < NC; c++) t[lane*37 + c] = src[(long)c*GRIDSZ*GRIDSZ];
    __syncwarp();
    float* dst = g_planesT + (long)cell0 * NC;
    #pragma unroll
    for (int k = 0; k < 9; k++) {
        int fo = (k*32 + lane) * 4;
        int cc = fo / NC, c = fo - cc*NC;
        *(float4*)(dst + fo) = make_float4(t[cc*37+c], t[cc*37+c+1], t[cc*37+c+2], t[cc*37+c+3]);
    }
}

__global__ void transpose_lines(const float* __restrict__ lines) {
    int t2 = blockIdx.x * blockDim.x + threadIdx.x;
    if (t2 < 3*GRIDSZ) {
        int j = t2 & (GRIDSZ-1), i = t2 >> 9;
        float* dst = g_linesT + t2*NC;
        const float* src = lines + (long)i*NC*GRIDSZ + j;
        #pragma unroll
        for (int c = 0; c < NC; c++) dst[c] = src[(long)c*GRIDSZ];
    }
}

__global__ void pack_weights_kernel(const float* __restrict__ W1, const float* __restrict__ W2) {
    int idx = blockIdx.x * blockDim.x + threadIdx.x;
    const int T1 = 256*136;          // 34816
    const int T2 = 160*264;          // 42240
    if (idx < T1) {
        int n = idx / 136, k = idx - n*136;
        g_W1h[idx] = (k < KIN) ? __float2half_rn(W1[k*HID + n]) : __float2half_rn(0.f);
    } else if (idx < T1 + T2) {
        int j = idx - T1;
        int n = j / 264, k = j - n*264;
        float v = (k < 256 && n < NOUT) ? W2[k*NOUT + n] : 0.f;
        g_W2h[j] = __float2half_rn(v);
    }
}

// ================= mma / ldmatrix helpers =================
__device__ __forceinline__ void mma_f16_k16(float c[4], unsigned a0, unsigned a1,
                                            unsigned a2, unsigned a3,
                                            unsigned b0, unsigned b1) {
    asm volatile(
        "mma.sync.aligned.m16n8k16.row.col.f32.f16.f16.f32 "
        "{%0,%1,%2,%3},{%4,%5,%6,%7},{%8,%9},{%0,%1,%2,%3};"
        : "+f"(c[0]), "+f"(c[1]), "+f"(c[2]), "+f"(c[3])
        : "r"(a0), "r"(a1), "r"(a2), "r"(a3), "r"(b0), "r"(b1));
}
__device__ __forceinline__ void mma_f16_k8(float c[4], unsigned a0, unsigned a1, unsigned b0) {
    asm volatile(
        "mma.sync.aligned.m16n8k8.row.col.f32.f16.f16.f32 "
        "{%0,%1,%2,%3},{%4,%5},{%6},{%0,%1,%2,%3};"
        : "+f"(c[0]), "+f"(c[1]), "+f"(c[2]), "+f"(c[3])
        : "r"(a0), "r"(a1), "r"(b0));
}
__device__ __forceinline__ void ldsm_x4(unsigned& r0, unsigned& r1, unsigned& r2, unsigned& r3,
                                        uint32_t a) {
    asm volatile("ldmatrix.sync.aligned.m8n8.x4.shared.b16 {%0,%1,%2,%3}, [%4];"
                 : "=r"(r0), "=r"(r1), "=r"(r2), "=r"(r3) : "r"(a));
}
__device__ __forceinline__ void ldsm_x2(unsigned& r0, unsigned& r1, uint32_t a) {
    asm volatile("ldmatrix.sync.aligned.m8n8.x2.shared.b16 {%0,%1}, [%2];"
                 : "=r"(r0), "=r"(r1) : "r"(a));
}

__device__ __forceinline__ float softplus100(float z) {
    float y = 100.f * z;
    return 0.01f * (fmaxf(y, 0.f) + __logf(1.f + __expf(-fabsf(y))));
}
__device__ __forceinline__ void cp16(uint32_t dst, const void* src) {
    asm volatile("cp.async.cg.shared.global [%0], [%1], 16;" :: "r"(dst), "l"(src));
}
__device__ __forceinline__ void cp_commit() { asm volatile("cp.async.commit_group;"); }
__device__ __forceinline__ void cp_wait0()  { asm volatile("cp.async.wait_group 0;" ::: "memory"); }

// ================= main fused kernel =================
__global__ void __launch_bounds__(NTHREADS, 1)
tensosdf_main(const float* __restrict__ xyz,
              const float* __restrict__ b1, const float* __restrict__ b2,
              float* __restrict__ out) {
    extern __shared__ char smem[];
    const uint32_t smem_u32 = (uint32_t)__cvta_generic_to_shared(smem);
    float* b1s = (float*)(smem + BY_B1S);
    float* b2s = (float*)(smem + BY_B2S);

    const int tid  = threadIdx.x;
    const int lane = tid & 31;
    const int warp = tid >> 5;
    const int pbase = blockIdx.x * TB;
    const int g = lane >> 2;
    const int t = lane & 3;

    // ---- biases ----
    if (tid < HID) b1s[tid] = b1[tid];
    else if (tid < HID + 160) { int c = tid - HID; b2s[c] = (c < NOUT) ? b2[c] : 0.f; }

    // ---- stage W1 image (69632 B = 4352 x 16B), overlaps gather ----
    for (int idx = tid; idx < 4352; idx += NTHREADS)
        cp16(smem_u32 + BY_W1 + (uint32_t)idx*16u, (const char*)g_W1h + idx*16);
    cp_commit();

    // ---- gather: warp handles 8 points, writes fp16 A1 (stride 272B) ----
    {
        const unsigned FULL = 0xffffffffu;
        float vload = 0.f;
        int base3 = (pbase + warp*8)*3;
        if (lane < 24) vload = xyz[base3 + lane];

        const int i_of = (lane < 9) ? 0 : ((lane < 18) ? 1 : 2);
        const int cj = (lane - i_of*9) * 4;
        const bool act = lane < 27;
        const int fcol = i_of*NC + cj;
        const int pcol = 108 + lane;

        #pragma unroll
        for (int pi = 0; pi < 8; pi++) {
            float x0 = __shfl_sync(FULL, vload, pi*3+0);
            float x1 = __shfl_sync(FULL, vload, pi*3+1);
            float x2 = __shfl_sync(FULL, vload, pi*3+2);
            float xn0 = 2.f*x0 - 1.f, xn1 = 2.f*x1 - 1.f, xn2 = 2.f*x2 - 1.f;
            int row = warp*8 + pi;
            char* rbase = smem + BY_A1 + row*SA1_B;

            if (act) {
                float gx = (i_of == 2) ? xn1 : xn0;
                float gy = (i_of == 0) ? xn1 : xn2;
                float gl = (i_of == 0) ? xn2 : ((i_of == 1) ? xn1 : xn0);
                float px = (gx + 1.f) * 0.5f * 511.f;
                float py = (gy + 1.f) * 0.5f * 511.f;
                float pl = (gl + 1.f) * 0.5f * 511.f;
                int ix = min(max((int)floorf(px), 0), 510);
                int iy = min(max((int)floorf(py), 0), 510);
                int il = min(max((int)floorf(pl), 0), 510);
                float wx = px - ix, wy = py - iy, wl = pl - il;
                const float* pb = g_planesT + (((i_of*GRIDSZ + iy)*GRIDSZ) + ix)*NC + cj;
                const float* lb = g_linesT + (i_of*GRIDSZ + il)*NC + cj;
                float4 f00 = *(const float4*)pb;
                float4 f01 = *(const float4*)(pb + NC);
                float4 f10 = *(const float4*)(pb + GRIDSZ*NC);
                float4 f11 = *(const float4*)(pb + GRIDSZ*NC + NC);
                float4 l0  = *(const float4*)lb;
                float4 l1  = *(const float4*)(lb + NC);
                float rx, ry, rz, rw;
                float fx0 = f00.x + wx*(f01.x - f00.x), fx1 = f10.x + wx*(f11.x - f10.x);
                rx = (fx0 + wy*(fx1 - fx0)) * (l0.x + wl*(l1.x - l0.x));
                fx0 = f00.y + wx*(f01.y - f00.y); fx1 = f10.y + wx*(f11.y - f10.y);
                ry = (fx0 + wy*(fx1 - fx0)) * (l0.y + wl*(l1.y - l0.y));
                fx0 = f00.z + wx*(f01.z - f00.z); fx1 = f10.z + wx*(f11.z - f10.z);
                rz = (fx0 + wy*(fx1 - fx0)) * (l0.z + wl*(l1.z - l0.z));
                fx0 = f00.w + wx*(f01.w - f00.w); fx1 = f10.w + wx*(f11.w - f10.w);
                rw = (fx0 + wy*(fx1 - fx0)) * (l0.w + wl*(l1.w - l0.w));
                *(__half2*)(rbase + fcol*2)     = __float22half2_rn(make_float2(rx, ry));
                *(__half2*)(rbase + fcol*2 + 4) = __float22half2_rn(make_float2(rz, rw));
            }

            float pv;
            if (lane < 3) pv = (lane == 0) ? xn0 : ((lane == 1) ? xn1 : xn2);
            else if (lane < 21) {
                int j = lane - 3, f = j / 6, rr = j - 6*f, d = rr % 3;
                float xv = ((d == 0) ? xn0 : ((d == 1) ? xn1 : xn2)) * (float)(1 << f);
                pv = (rr < 3) ? __sinf(xv) : __cosf(xv);
            } else pv = 0.f;
            if (pcol < K1PAD)
                *(__half*)(rbase + pcol*2) = __float2half_rn(pv);
        }
    }

    cp_wait0();
    __syncthreads();

    // ================= GEMM1: 16 warps = 4m(32 rows) x 4n(64 cols), ldmatrix =================
    const int mt = warp & 3;
    const int nq = warp >> 2;          // 0..3
    const int arow = mt * 32;

    // ldmatrix lane geometry: sel = lane>>3, row = (lane&7) + (sel&1)*8, koff16 = (lane>>4)*16B
    const int lrow  = (lane & 7) + ((lane >> 3) & 1) * 8;
    const int koffb = (lane >> 4) * 16;

    const uint32_t aAddr1 = smem_u32 + BY_A1 + (uint32_t)(arow + lrow)*SA1_B + koffb;
    const uint32_t bAddr1 = smem_u32 + BY_W1 + (uint32_t)(nq*64 + lrow)*SA1_B + koffb;
    // tails (k=128..135): lanes 0-15 supply addresses (koff must be 0 for x2)
    const uint32_t aT1 = smem_u32 + BY_A1 + (uint32_t)(arow + lrow)*SA1_B + 256;
    const uint32_t bT1 = smem_u32 + BY_W1 + (uint32_t)(nq*64 + lrow)*SA1_B + 256;

    float acc[2][8][4];
    #pragma unroll
    for (int i = 0; i < 2; i++)
        #pragma unroll
        for (int j = 0; j < 8; j++)
            #pragma unroll
            for (int q = 0; q < 4; q++) acc[i][j][q] = 0.f;

    #pragma unroll
    for (int ks = 0; ks < 8; ks++) {
        unsigned a0, a1, a2, a3, a4, a5, a6, a7;
        ldsm_x4(a0, a1, a2, a3, aAddr1 + ks*32);
        ldsm_x4(a4, a5, a6, a7, aAddr1 + 16*SA1_B + ks*32);
        #pragma unroll
        for (int p = 0; p < 4; p++) {
            unsigned b0, b1, b2, b3;
            ldsm_x4(b0, b1, b2, b3, bAddr1 + (uint32_t)p*16*SA1_B + ks*32);
            mma_f16_k16(acc[0][2*p],   a0, a1, a2, a3, b0, b2);
            mma_f16_k16(acc[0][2*p+1], a0, a1, a2, a3, b1, b3);
            mma_f16_k16(acc[1][2*p],   a4, a5, a6, a7, b0, b2);
            mma_f16_k16(acc[1][2*p+1], a4, a5, a6, a7, b1, b3);
        }
    }
    {   // k8 tail
        unsigned a0, a1, a4, a5;
        ldsm_x2(a0, a1, aT1);
        ldsm_x2(a4, a5, aT1 + 16*SA1_B);
        #pragma unroll
        for (int p = 0; p < 4; p++) {
            unsigned b0, b1;
            ldsm_x2(b0, b1, bT1 + (uint32_t)p*16*SA1_B);
            mma_f16_k8(acc[0][2*p],   a0, a1, b0);
            mma_f16_k8(acc[0][2*p+1], a0, a1, b1);
            mma_f16_k8(acc[1][2*p],   a4, a5, b0);
            mma_f16_k8(acc[1][2*p+1], a4, a5, b1);
        }
    }

    __syncthreads();   // all W1/A1 reads done

    // stage W2 image (84480 B = 5280 x 16B) into [0, 84480)
    for (int idx = tid; idx < 5280; idx += NTHREADS)
        cp16(smem_u32 + (uint32_t)idx*16u, (const char*)g_W2h + idx*16);
    cp_commit();

    // epilogue 1: bias + softplus -> fp16 A2 (stride 528B)
    #pragma unroll
    for (int mf = 0; mf < 2; mf++) {
        #pragma unroll
        for (int nf = 0; nf < 8; nf++) {
            int col = nq*64 + nf*8 + 2*t;
            float bb0 = b1s[col], bb1 = b1s[col+1];
            int row0 = arow + mf*16 + g;
            float r0 = softplus100(acc[mf][nf][0] + bb0);
            float r1 = softplus100(acc[mf][nf][1] + bb1);
            float r2 = softplus100(acc[mf][nf][2] + bb0);
            float r3 = softplus100(acc[mf][nf][3] + bb1);
            *(__half2*)(smem + BY_A2 + row0*SA2_B + col*2)     = __float22half2_rn(make_float2(r0, r1));
            *(__half2*)(smem + BY_A2 + (row0+8)*SA2_B + col*2) = __float22half2_rn(make_float2(r2, r3));
        }
    }

    cp_wait0();
    __syncthreads();

    // ================= GEMM2: 16 warps = 4m(32) x 4n(40), ldmatrix =================
    const uint32_t aAddr2 = smem_u32 + BY_A2 + (uint32_t)(arow + lrow)*SA2_B + koffb;
    const uint32_t bAddr2 = smem_u32 + 0 + (uint32_t)(nq*40 + lrow)*SA2_B + koffb;
    // nf4 (n8k16) x2: lanes 0-7 -> k0 block, lanes 8-15 -> k8 block
    const uint32_t bAddr2e = smem_u32 + 0 + (uint32_t)(nq*40 + 32 + (lane & 7))*SA2_B
                           + ((lane >> 3) & 1) * 16;

    float acc2[2][5][4];
    #pragma unroll
    for (int i = 0; i < 2; i++)
        #pragma unroll
        for (int j = 0; j < 5; j++)
            #pragma unroll
            for (int q = 0; q < 4; q++) acc2[i][j][q] = 0.f;

    #pragma unroll
    for (int ks = 0; ks < 16; ks++) {
        unsigned a0, a1, a2, a3, a4, a5, a6, a7;
        ldsm_x4(a0, a1, a2, a3, aAddr2 + ks*32);
        ldsm_x4(a4, a5, a6, a7, aAddr2 + 16*SA2_B + ks*32);
        #pragma unroll
        for (int p = 0; p < 2; p++) {
            unsigned b0, b1, b2, b3;
            ldsm_x4(b0, b1, b2, b3, bAddr2 + (uint32_t)p*16*SA2_B + ks*32);
            mma_f16_k16(acc2[0][2*p],   a0, a1, a2, a3, b0, b2);
            mma_f16_k16(acc2[0][2*p+1], a0, a1, a2, a3, b1, b3);
            mma_f16_k16(acc2[1][2*p],   a4, a5, a6, a7, b0, b2);
            mma_f16_k16(acc2[1][2*p+1], a4, a5, a6, a7, b1, b3);
        }
        {
            unsigned b0, b1;
            ldsm_x2(b0, b1, bAddr2e + ks*32);
            mma_f16_k16(acc2[0][4], a0, a1, a2, a3, b0, b1);
            mma_f16_k16(acc2[1][4], a4, a5, a6, a7, b0, b1);
        }
    }

    // epilogue 2: bias + store
    #pragma unroll
    for (int mf = 0; mf < 2; mf++) {
        #pragma unroll
        for (int nf = 0; nf < 5; nf++) {
            int col = nq*40 + nf*8 + 2*t;
            float o0 = acc2[mf][nf][0] + b2s[col];
            float o1 = acc2[mf][nf][1] + b2s[col+1];
            float o2 = acc2[mf][nf][2] + b2s[col];
            float o3 = acc2[mf][nf][3] + b2s[col+1];
            int r0 = (pbase + arow + mf*16 + g) * NOUT;
            int r1 = r0 + 8*NOUT;
            if (col < NOUT)     { out[r0 + col]     = o0; out[r1 + col]     = o2; }
            if (col + 1 < NOUT) { out[r0 + col + 1] = o1; out[r1 + col + 1] = o3; }
        }
    }
}

extern "C" void kernel_launch(void* const* d_in, const int* in_sizes, int n_in,
                              void* d_out, int out_size) {
    const float* xyz    = (const float*)d_in[0];
    const float* planes = (const float*)d_in[1];
    const float* lines  = (const float*)d_in[2];
    const float* W1     = (const float*)d_in[3];
    const float* b1     = (const float*)d_in[4];
    const float* W2     = (const float*)d_in[5];
    const float* b2     = (const float*)d_in[6];
    float* out = (float*)d_out;

    static bool attr_set = false;
    if (!attr_set) {
        cudaFuncSetAttribute(tensosdf_main,
                             cudaFuncAttributeMaxDynamicSharedMemorySize, SMEM_BYTES);
        attr_set = true;
    }

    transpose_planes<<<3072, 256>>>(planes);
    transpose_lines<<<6, 256>>>(lines);
    const int npack = 256*136 + 160*264;
    pack_weights_kernel<<<(npack + 255) / 256, 256>>>(W1, W2);
    tensosdf_main<<<NPTS / TB, NTHREADS, SMEM_BYTES>>>(xyz, b1, b2, out);
}

// round 11
// speedup vs baseline: 1.1691x; 1.0623x over previous
#include <cuda_runtime.h>
#include <cuda_fp16.h>
#include <math.h>
#include <stdint.h>

#define NPTS      524288
#define GRIDSZ    512
#define NC        36
#define KIN       129
#define K1PAD     136
#define HID       256
#define NOUT      129
#define TB        64
#define NTHREADS  256

// ---- smem byte layout (per CTA, 2 CTAs/SM) ----
// phase1: W1 [0,69632) ; A1 [76032,93440)
// phase2: W2 [0,76032) ; A2 [76032,109824)   (A2 aliases A1; lifetimes disjoint)
// biases: b1 f32 [109824,110848) ; b2 f32 [110848,111424)
#define BY_W1   0
#define BY_W2   0
#define BY_A1   76032
#define BY_A2   76032
#define BY_B1S  109824
#define BY_B2S  110848
#define SMEM_BYTES 111424

#define SA1_B 272         // A1/W1 row stride bytes (136 halfs); 272%128=16 -> ldsm conflict-free
#define SA2_B 528         // A2/W2 row stride bytes (264 halfs); 528%128=16 -> ldsm conflict-free
#define N2PAD 144         // W2 n-padding (2 groups x 72)

__device__ float g_planesT[3*GRIDSZ*GRIDSZ*NC];   // [i][y][x][c]
__device__ float g_linesT[3*GRIDSZ*NC];           // [i][l][c]
__device__ __align__(16) __half g_W1h[256*136];   // [n][k], fp16, zero-padded k>=129
__device__ __align__(16) __half g_W2h[N2PAD*264]; // [n][k], fp16, zero-padded n>=129 / k>=256

// ================= prep kernels =================
__global__ void __launch_bounds__(256) transpose_planes(const float* __restrict__ planes) {
    __shared__ float tile[8][32*37];
    int wid = threadIdx.x >> 5, lane = threadIdx.x & 31;
    int cell0 = (blockIdx.x * 8 + wid) * 32;
    int i = cell0 / (GRIDSZ*GRIDSZ);
    int rem = cell0 - i*GRIDSZ*GRIDSZ;
    int y = rem >> 9, x0 = rem & (GRIDSZ-1);
    const float* src = planes + (long)i*NC*GRIDSZ*GRIDSZ + (long)y*GRIDSZ + x0 + lane;
    float* t = tile[wid];
    #pragma unroll
    for (int c = 0; c < NC; c++) t[lane*37 + c] = src[(long)c*GRIDSZ*GRIDSZ];
    __syncwarp();
    float* dst = g_planesT + (long)cell0 * NC;
    #pragma unroll
    for (int k = 0; k < 9; k++) {
        int fo = (k*32 + lane) * 4;
        int cc = fo / NC, c = fo - cc*NC;
        *(float4*)(dst + fo) = make_float4(t[cc*37+c], t[cc*37+c+1], t[cc*37+c+2], t[cc*37+c+3]);
    }
}

__global__ void transpose_lines(const float* __restrict__ lines) {
    int t2 = blockIdx.x * blockDim.x + threadIdx.x;
    if (t2 < 3*GRIDSZ) {
        int j = t2 & (GRIDSZ-1), i = t2 >> 9;
        float* dst = g_linesT + t2*NC;
        const float* src = lines + (long)i*NC*GRIDSZ + j;
        #pragma unroll
        for (int c = 0; c < NC; c++) dst[c] = src[(long)c*GRIDSZ];
    }
}

__global__ void pack_weights_kernel(const float* __restrict__ W1, const float* __restrict__ W2) {
    int idx = blockIdx.x * blockDim.x + threadIdx.x;
    const int T1 = 256*136;          // 34816
    const int T2 = N2PAD*264;        // 38016
    if (idx < T1) {
        int n = idx / 136, k = idx - n*136;
        g_W1h[idx] = (k < KIN) ? __float2half_rn(W1[k*HID + n]) : __float2half_rn(0.f);
    } else if (idx < T1 + T2) {
        int j = idx - T1;
        int n = j / 264, k = j - n*264;
        float v = (k < 256 && n < NOUT) ? W2[k*NOUT + n] : 0.f;
        g_W2h[j] = __float2half_rn(v);
    }
}

// ================= mma / ldmatrix helpers =================
__device__ __forceinline__ void mma_f16_k16(float c[4], unsigned a0, unsigned a1,
                                            unsigned a2, unsigned a3,
                                            unsigned b0, unsigned b1) {
    asm volatile(
        "mma.sync.aligned.m16n8k16.row.col.f32.f16.f16.f32 "
        "{%0,%1,%2,%3},{%4,%5,%6,%7},{%8,%9},{%0,%1,%2,%3};"
        : "+f"(c[0]), "+f"(c[1]), "+f"(c[2]), "+f"(c[3])
        : "r"(a0), "r"(a1), "r"(a2), "r"(a3), "r"(b0), "r"(b1));
}
__device__ __forceinline__ void mma_f16_k8(float c[4], unsigned a0, unsigned a1, unsigned b0) {
    asm volatile(
        "mma.sync.aligned.m16n8k8.row.col.f32.f16.f16.f32 "
        "{%0,%1,%2,%3},{%4,%5},{%6},{%0,%1,%2,%3};"
        : "+f"(c[0]), "+f"(c[1]), "+f"(c[2]), "+f"(c[3])
        : "r"(a0), "r"(a1), "r"(b0));
}
__device__ __forceinline__ void ldsm_x4(unsigned& r0, unsigned& r1, unsigned& r2, unsigned& r3,
                                        uint32_t a) {
    asm volatile("ldmatrix.sync.aligned.m8n8.x4.shared.b16 {%0,%1,%2,%3}, [%4];"
                 : "=r"(r0), "=r"(r1), "=r"(r2), "=r"(r3) : "r"(a));
}
__device__ __forceinline__ void ldsm_x2(unsigned& r0, unsigned& r1, uint32_t a) {
    asm volatile("ldmatrix.sync.aligned.m8n8.x2.shared.b16 {%0,%1}, [%2];"
                 : "=r"(r0), "=r"(r1) : "r"(a));
}

__device__ __forceinline__ float softplus100(float z) {
    float y = 100.f * z;
    return 0.01f * (fmaxf(y, 0.f) + __logf(1.f + __expf(-fabsf(y))));
}
__device__ __forceinline__ void cp16(uint32_t dst, const void* src) {
    asm volatile("cp.async.cg.shared.global [%0], [%1], 16;" :: "r"(dst), "l"(src));
}
__device__ __forceinline__ void cp_commit() { asm volatile("cp.async.commit_group;"); }
__device__ __forceinline__ void cp_wait0()  { asm volatile("cp.async.wait_group 0;" ::: "memory"); }

// ================= main fused kernel (2 CTAs/SM) =================
__global__ void __launch_bounds__(NTHREADS, 2)
tensosdf_main(const float* __restrict__ xyz,
              const float* __restrict__ b1, const float* __restrict__ b2,
              float* __restrict__ out) {
    extern __shared__ char smem[];
    const uint32_t smem_u32 = (uint32_t)__cvta_generic_to_shared(smem);
    float* b1s = (float*)(smem + BY_B1S);
    float* b2s = (float*)(smem + BY_B2S);

    const int tid  = threadIdx.x;
    const int lane = tid & 31;
    const int warp = tid >> 5;            // 0..7
    const int pbase = blockIdx.x * TB;
    const int g = lane >> 2;
    const int t = lane & 3;

    // ---- biases ----
    b1s[tid] = b1[tid];
    if (tid < N2PAD) b2s[tid] = (tid < NOUT) ? b2[tid] : 0.f;

    // ---- stage W1 image (69632 B = 4352 x 16B), overlaps gather ----
    for (int idx = tid; idx < 4352; idx += NTHREADS)
        cp16(smem_u32 + BY_W1 + (uint32_t)idx*16u, (const char*)g_W1h + idx*16);
    cp_commit();

    // ---- gather: warp handles 8 points, writes fp16 A1 (stride 272B) ----
    {
        const unsigned FULL = 0xffffffffu;
        float vload = 0.f;
        int base3 = (pbase + warp*8)*3;
        if (lane < 24) vload = xyz[base3 + lane];

        const int i_of = (lane < 9) ? 0 : ((lane < 18) ? 1 : 2);
        const int cj = (lane - i_of*9) * 4;
        const bool act = lane < 27;
        const int fcol = i_of*NC + cj;
        const int pcol = 108 + lane;

        #pragma unroll
        for (int pi = 0; pi < 8; pi++) {
            float x0 = __shfl_sync(FULL, vload, pi*3+0);
            float x1 = __shfl_sync(FULL, vload, pi*3+1);
            float x2 = __shfl_sync(FULL, vload, pi*3+2);
            float xn0 = 2.f*x0 - 1.f, xn1 = 2.f*x1 - 1.f, xn2 = 2.f*x2 - 1.f;
            int row = warp*8 + pi;
            char* rbase = smem + BY_A1 + row*SA1_B;

            if (act) {
                float gx = (i_of == 2) ? xn1 : xn0;
                float gy = (i_of == 0) ? xn1 : xn2;
                float gl = (i_of == 0) ? xn2 : ((i_of == 1) ? xn1 : xn0);
                float px = (gx + 1.f) * 0.5f * 511.f;
                float py = (gy + 1.f) * 0.5f * 511.f;
                float pl = (gl + 1.f) * 0.5f * 511.f;
                int ix = min(max((int)floorf(px), 0), 510);
                int iy = min(max((int)floorf(py), 0), 510);
                int il = min(max((int)floorf(pl), 0), 510);
                float wx = px - ix, wy = py - iy, wl = pl - il;
                const float* pb = g_planesT + (((i_of*GRIDSZ + iy)*GRIDSZ) + ix)*NC + cj;
                const float* lb = g_linesT + (i_of*GRIDSZ + il)*NC + cj;
                float4 f00 = *(const float4*)pb;
                float4 f01 = *(const float4*)(pb + NC);
                float4 f10 = *(const float4*)(pb + GRIDSZ*NC);
                float4 f11 = *(const float4*)(pb + GRIDSZ*NC + NC);
                float4 l0  = *(const float4*)lb;
                float4 l1  = *(const float4*)(lb + NC);
                float rx, ry, rz, rw;
                float fx0 = f00.x + wx*(f01.x - f00.x), fx1 = f10.x + wx*(f11.x - f10.x);
                rx = (fx0 + wy*(fx1 - fx0)) * (l0.x + wl*(l1.x - l0.x));
                fx0 = f00.y + wx*(f01.y - f00.y); fx1 = f10.y + wx*(f11.y - f10.y);
                ry = (fx0 + wy*(fx1 - fx0)) * (l0.y + wl*(l1.y - l0.y));
                fx0 = f00.z + wx*(f01.z - f00.z); fx1 = f10.z + wx*(f11.z - f10.z);
                rz = (fx0 + wy*(fx1 - fx0)) * (l0.z + wl*(l1.z - l0.z));
                fx0 = f00.w + wx*(f01.w - f00.w); fx1 = f10.w + wx*(f11.w - f10.w);
                rw = (fx0 + wy*(fx1 - fx0)) * (l0.w + wl*(l1.w - l0.w));
                *(__half2*)(rbase + fcol*2)     = __float22half2_rn(make_float2(rx, ry));
                *(__half2*)(rbase + fcol*2 + 4) = __float22half2_rn(make_float2(rz, rw));
            }

            float pv;
            if (lane < 3) pv = (lane == 0) ? xn0 : ((lane == 1) ? xn1 : xn2);
            else if (lane < 21) {
                int j = lane - 3, f = j / 6, rr = j - 6*f, d = rr % 3;
                float xv = ((d == 0) ? xn0 : ((d == 1) ? xn1 : xn2)) * (float)(1 << f);
                pv = (rr < 3) ? __sinf(xv) : __cosf(xv);
            } else pv = 0.f;
            if (pcol < K1PAD)
                *(__half*)(rbase + pcol*2) = __float2half_rn(pv);
        }
    }

    cp_wait0();
    __syncthreads();

    // ================= GEMM1: 8 warps = 2m(32 rows) x 4n(64 cols), ldmatrix =================
    const int mt = warp & 1;
    const int nq = warp >> 1;          // 0..3
    const int arow = mt * 32;

    const int lrow  = (lane & 7) + ((lane >> 3) & 1) * 8;
    const int koffb = (lane >> 4) * 16;

    const uint32_t aAddr1 = smem_u32 + BY_A1 + (uint32_t)(arow + lrow)*SA1_B + koffb;
    const uint32_t bAddr1 = smem_u32 + BY_W1 + (uint32_t)(nq*64 + lrow)*SA1_B + koffb;
    const uint32_t aT1 = smem_u32 + BY_A1 + (uint32_t)(arow + lrow)*SA1_B + 256;
    const uint32_t bT1 = smem_u32 + BY_W1 + (uint32_t)(nq*64 + lrow)*SA1_B + 256;

    float acc[2][8][4];
    #pragma unroll
    for (int i = 0; i < 2; i++)
        #pragma unroll
        for (int j = 0; j < 8; j++)
            #pragma unroll
            for (int q = 0; q < 4; q++) acc[i][j][q] = 0.f;

    #pragma unroll
    for (int ks = 0; ks < 8; ks++) {
        unsigned a0, a1, a2, a3, a4, a5, a6, a7;
        ldsm_x4(a0, a1, a2, a3, aAddr1 + ks*32);
        ldsm_x4(a4, a5, a6, a7, aAddr1 + 16*SA1_B + ks*32);
        #pragma unroll
        for (int p = 0; p < 4; p++) {
            unsigned b0, b1, b2, b3;
            ldsm_x4(b0, b1, b2, b3, bAddr1 + (uint32_t)p*16*SA1_B + ks*32);
            mma_f16_k16(acc[0][2*p],   a0, a1, a2, a3, b0, b2);
            mma_f16_k16(acc[0][2*p+1], a0, a1, a2, a3, b1, b3);
            mma_f16_k16(acc[1][2*p],   a4, a5, a6, a7, b0, b2);
            mma_f16_k16(acc[1][2*p+1], a4, a5, a6, a7, b1, b3);
        }
    }
    {   // k8 tail: k = 128..135
        unsigned a0, a1, a4, a5;
        ldsm_x2(a0, a1, aT1);
        ldsm_x2(a4, a5, aT1 + 16*SA1_B);
        #pragma unroll
        for (int p = 0; p < 4; p++) {
            unsigned b0, b1;
            ldsm_x2(b0, b1, bT1 + (uint32_t)p*16*SA1_B);
            mma_f16_k8(acc[0][2*p],   a0, a1, b0);
            mma_f16_k8(acc[0][2*p+1], a0, a1, b1);
            mma_f16_k8(acc[1][2*p],   a4, a5, b0);
            mma_f16_k8(acc[1][2*p+1], a4, a5, b1);
        }
    }

    __syncthreads();   // all W1/A1 reads done

    // stage W2 image (144 x 528 B = 4752 x 16B) into [0, 76032)
    for (int idx = tid; idx < 4752; idx += NTHREADS)
        cp16(smem_u32 + BY_W2 + (uint32_t)idx*16u, (const char*)g_W2h + idx*16);
    cp_commit();

    // epilogue 1: bias + softplus -> fp16 A2 (stride 528B)
    #pragma unroll
    for (int mf = 0; mf < 2; mf++) {
        #pragma unroll
        for (int nf = 0; nf < 8; nf++) {
            int col = nq*64 + nf*8 + 2*t;
            float bb0 = b1s[col], bb1 = b1s[col+1];
            int row0 = arow + mf*16 + g;
            float r0 = softplus100(acc[mf][nf][0] + bb0);
            float r1 = softplus100(acc[mf][nf][1] + bb1);
            float r2 = softplus100(acc[mf][nf][2] + bb0);
            float r3 = softplus100(acc[mf][nf][3] + bb1);
            *(__half2*)(smem + BY_A2 + row0*SA2_B + col*2)     = __float22half2_rn(make_float2(r0, r1));
            *(__half2*)(smem + BY_A2 + (row0+8)*SA2_B + col*2) = __float22half2_rn(make_float2(r2, r3));
        }
    }

    cp_wait0();
    __syncthreads();

    // ================= GEMM2: 8 warps = 4m(16 rows) x 2n(72 cols), ldmatrix =================
    const int mt2 = warp & 3;
    const int nh2 = warp >> 2;         // 0..1
    const int arow2 = mt2 * 16;

    const uint32_t aAddr2 = smem_u32 + BY_A2 + (uint32_t)(arow2 + lrow)*SA2_B + koffb;
    const uint32_t bAddr2 = smem_u32 + BY_W2 + (uint32_t)(nh2*72 + lrow)*SA2_B + koffb;
    const uint32_t bAddr2e = smem_u32 + BY_W2 + (uint32_t)(nh2*72 + 64 + (lane & 7))*SA2_B
                           + ((lane >> 3) & 1) * 16;

    float acc2[9][4];
    #pragma unroll
    for (int j = 0; j < 9; j++)
        #pragma unroll
        for (int q = 0; q < 4; q++) acc2[j][q] = 0.f;

    #pragma unroll
    for (int ks = 0; ks < 16; ks++) {
        unsigned a0, a1, a2, a3;
        ldsm_x4(a0, a1, a2, a3, aAddr2 + ks*32);
        #pragma unroll
        for (int p = 0; p < 4; p++) {
            unsigned b0, b1, b2, b3;
            ldsm_x4(b0, b1, b2, b3, bAddr2 + (uint32_t)p*16*SA2_B + ks*32);
            mma_f16_k16(acc2[2*p],   a0, a1, a2, a3, b0, b2);
            mma_f16_k16(acc2[2*p+1], a0, a1, a2, a3, b1, b3);
        }
        {
            unsigned b0, b1;
            ldsm_x2(b0, b1, bAddr2e + ks*32);
            mma_f16_k16(acc2[8], a0, a1, a2, a3, b0, b1);
        }
    }

    // epilogue 2: bias + store
    #pragma unroll
    for (int nf = 0; nf < 9; nf++) {
        int col = nh2*72 + nf*8 + 2*t;
        float o0 = acc2[nf][0] + b2s[col];
        float o1 = acc2[nf][1] + b2s[col+1];
        float o2 = acc2[nf][2] + b2s[col];
        float o3 = acc2[nf][3] + b2s[col+1];
        int r0 = (pbase + arow2 + g) * NOUT;
        int r1 = r0 + 8*NOUT;
        if (col < NOUT)     { out[r0 + col]     = o0; out[r1 + col]     = o2; }
        if (col + 1 < NOUT) { out[r0 + col + 1] = o1; out[r1 + col + 1] = o3; }
    }
}

extern "C" void kernel_launch(void* const* d_in, const int* in_sizes, int n_in,
                              void* d_out, int out_size) {
    const float* xyz    = (const float*)d_in[0];
    const float* planes = (const float*)d_in[1];
    const float* lines  = (const float*)d_in[2];
    const float* W1     = (const float*)d_in[3];
    const float* b1     = (const float*)d_in[4];
    const float* W2     = (const float*)d_in[5];
    const float* b2     = (const float*)d_in[6];
    float* out = (float*)d_out;

    static bool attr_set = false;
    if (!attr_set) {
        cudaFuncSetAttribute(tensosdf_main,
                             cudaFuncAttributeMaxDynamicSharedMemorySize, SMEM_BYTES);
        attr_set = true;
    }

    transpose_planes<<<3072, 256>>>(planes);
    transpose_lines<<<6, 256>>>(lines);
    const int npack = 256*136 + N2PAD*264;
    pack_weights_kernel<<<(npack + 255) / 256, 256>>>(W1, W2);
    tensosdf_main<<<NPTS / TB, NTHREADS, SMEM_BYTES>>>(xyz, b1, b2, out);
}

// round 12
// speedup vs baseline: 1.2995x; 1.1115x over previous
#include <cuda_runtime.h>
#include <cuda_fp16.h>
#include <math.h>
#include <stdint.h>

#define NPTS      524288
#define GRIDSZ    512
#define NC        36
#define KIN       129
#define K1PAD     136
#define HID       256
#define NOUT      129
#define TB        64
#define NTHREADS  256

// ---- smem byte layout (per CTA, 2 CTAs/SM) ----
#define BY_W1   0
#define BY_W2   0
#define BY_A1   76032
#define BY_A2   76032
#define BY_B1S  109824
#define BY_B2S  110848
#define SMEM_BYTES 111424

#define SA1_B 272         // A1/W1 row stride bytes; 272%128=16 -> ldsm conflict-free
#define SA2_B 528         // A2/W2 row stride bytes; 528%128=16 -> ldsm conflict-free
#define N2PAD 144

__device__ __align__(16) __half g_planesTh[3*GRIDSZ*GRIDSZ*NC]; // [i][y][x][c] fp16
__device__ __align__(16) __half g_linesTh[3*GRIDSZ*NC];         // [i][l][c] fp16
__device__ __align__(16) __half g_W1h[256*136];   // [n][k], fp16, zero-padded k>=129
__device__ __align__(16) __half g_W2h[N2PAD*264]; // [n][k], fp16, zero-padded

// ================= prep kernels =================
__global__ void __launch_bounds__(256) transpose_planes(const float* __restrict__ planes) {
    __shared__ float tile[8][32*37];
    int wid = threadIdx.x >> 5, lane = threadIdx.x & 31;
    int cell0 = (blockIdx.x * 8 + wid) * 32;
    int i = cell0 / (GRIDSZ*GRIDSZ);
    int rem = cell0 - i*GRIDSZ*GRIDSZ;
    int y = rem >> 9, x0 = rem & (GRIDSZ-1);
    const float* src = planes + (long)i*NC*GRIDSZ*GRIDSZ + (long)y*GRIDSZ + x0 + lane;
    float* t = tile[wid];
    #pragma unroll
    for (int c = 0; c < NC; c++) t[lane*37 + c] = src[(long)c*GRIDSZ*GRIDSZ];
    __syncwarp();
    __half2* dst = (__half2*)(g_planesTh + (long)cell0 * NC);
    #pragma unroll
    for (int k = 0; k < 18; k++) {
        int h2i = k*32 + lane;            // 0..575 half2 units (32 cells x 18)
        int e0 = h2i*2;
        int cc = e0 / NC, c = e0 - cc*NC; // pairs never cross cells (NC even)
        dst[h2i] = __floats2half2_rn(t[cc*37+c], t[cc*37+c+1]);
    }
}

__global__ void transpose_lines(const float* __restrict__ lines) {
    int t2 = blockIdx.x * blockDim.x + threadIdx.x;
    if (t2 < 3*GRIDSZ) {
        int j = t2 & (GRIDSZ-1), i = t2 >> 9;
        __half* dst = g_linesTh + t2*NC;
        const float* src = lines + (long)i*NC*GRIDSZ + j;
        #pragma unroll
        for (int c = 0; c < NC; c++) dst[c] = __float2half_rn(src[(long)c*GRIDSZ]);
    }
}

__global__ void pack_weights_kernel(const float* __restrict__ W1, const float* __restrict__ W2) {
    int idx = blockIdx.x * blockDim.x + threadIdx.x;
    const int T1 = 256*136;
    const int T2 = N2PAD*264;
    if (idx < T1) {
        int n = idx / 136, k = idx - n*136;
        g_W1h[idx] = (k < KIN) ? __float2half_rn(W1[k*HID + n]) : __float2half_rn(0.f);
    } else if (idx < T1 + T2) {
        int j = idx - T1;
        int n = j / 264, k = j - n*264;
        float v = (k < 256 && n < NOUT) ? W2[k*NOUT + n] : 0.f;
        g_W2h[j] = __float2half_rn(v);
    }
}

// ================= mma / ldmatrix helpers =================
__device__ __forceinline__ void mma_f16_k16(float c[4], unsigned a0, unsigned a1,
                                            unsigned a2, unsigned a3,
                                            unsigned b0, unsigned b1) {
    asm volatile(
        "mma.sync.aligned.m16n8k16.row.col.f32.f16.f16.f32 "
        "{%0,%1,%2,%3},{%4,%5,%6,%7},{%8,%9},{%0,%1,%2,%3};"
        : "+f"(c[0]), "+f"(c[1]), "+f"(c[2]), "+f"(c[3])
        : "r"(a0), "r"(a1), "r"(a2), "r"(a3), "r"(b0), "r"(b1));
}
__device__ __forceinline__ void mma_f16_k8(float c[4], unsigned a0, unsigned a1, unsigned b0) {
    asm volatile(
        "mma.sync.aligned.m16n8k8.row.col.f32.f16.f16.f32 "
        "{%0,%1,%2,%3},{%4,%5},{%6},{%0,%1,%2,%3};"
        : "+f"(c[0]), "+f"(c[1]), "+f"(c[2]), "+f"(c[3])
        : "r"(a0), "r"(a1), "r"(b0));
}
__device__ __forceinline__ void ldsm_x4(unsigned& r0, unsigned& r1, unsigned& r2, unsigned& r3,
                                        uint32_t a) {
    asm volatile("ldmatrix.sync.aligned.m8n8.x4.shared.b16 {%0,%1,%2,%3}, [%4];"
                 : "=r"(r0), "=r"(r1), "=r"(r2), "=r"(r3) : "r"(a));
}
__device__ __forceinline__ void ldsm_x2(unsigned& r0, unsigned& r1, uint32_t a) {
    asm volatile("ldmatrix.sync.aligned.m8n8.x2.shared.b16 {%0,%1}, [%2];"
                 : "=r"(r0), "=r"(r1) : "r"(a));
}

__device__ __forceinline__ float softplus100(float z) {
    float y = 100.f * z;
    return 0.01f * (fmaxf(y, 0.f) + __logf(1.f + __expf(-fabsf(y))));
}
__device__ __forceinline__ void cp16(uint32_t dst, const void* src) {
    asm volatile("cp.async.cg.shared.global [%0], [%1], 16;" :: "r"(dst), "l"(src));
}
__device__ __forceinline__ void cp_commit() { asm volatile("cp.async.commit_group;"); }
__device__ __forceinline__ void cp_wait0()  { asm volatile("cp.async.wait_group 0;" ::: "memory"); }

// ================= main fused kernel (2 CTAs/SM) =================
__global__ void __launch_bounds__(NTHREADS, 2)
tensosdf_main(const float* __restrict__ xyz,
              const float* __restrict__ b1, const float* __restrict__ b2,
              float* __restrict__ out) {
    extern __shared__ char smem[];
    const uint32_t smem_u32 = (uint32_t)__cvta_generic_to_shared(smem);
    float* b1s = (float*)(smem + BY_B1S);
    float* b2s = (float*)(smem + BY_B2S);

    const int tid  = threadIdx.x;
    const int lane = tid & 31;
    const int warp = tid >> 5;            // 0..7
    const int pbase = blockIdx.x * TB;
    const int g = lane >> 2;
    const int t = lane & 3;

    // ---- biases ----
    b1s[tid] = b1[tid];
    if (tid < N2PAD) b2s[tid] = (tid < NOUT) ? b2[tid] : 0.f;

    // ---- stage W1 image (69632 B = 4352 x 16B), overlaps gather ----
    for (int idx = tid; idx < 4352; idx += NTHREADS)
        cp16(smem_u32 + BY_W1 + (uint32_t)idx*16u, (const char*)g_W1h + idx*16);
    cp_commit();

    // ---- gather: warp handles 8 points, fp16 tables, writes fp16 A1 ----
    {
        const unsigned FULL = 0xffffffffu;
        float vload = 0.f;
        int base3 = (pbase + warp*8)*3;
        if (lane < 24) vload = xyz[base3 + lane];

        const int i_of = (lane < 9) ? 0 : ((lane < 18) ? 1 : 2);
        const int cj = (lane - i_of*9) * 4;
        const bool act = lane < 27;
        const int fcol = i_of*NC + cj;
        const int pcol = 108 + lane;

        #pragma unroll
        for (int pi = 0; pi < 8; pi++) {
            float x0 = __shfl_sync(FULL, vload, pi*3+0);
            float x1 = __shfl_sync(FULL, vload, pi*3+1);
            float x2 = __shfl_sync(FULL, vload, pi*3+2);
            float xn0 = 2.f*x0 - 1.f, xn1 = 2.f*x1 - 1.f, xn2 = 2.f*x2 - 1.f;
            int row = warp*8 + pi;
            char* rbase = smem + BY_A1 + row*SA1_B;

            if (act) {
                float gx = (i_of == 2) ? xn1 : xn0;
                float gy = (i_of == 0) ? xn1 : xn2;
                float gl = (i_of == 0) ? xn2 : ((i_of == 1) ? xn1 : xn0);
                float px = (gx + 1.f) * 0.5f * 511.f;
                float py = (gy + 1.f) * 0.5f * 511.f;
                float pl = (gl + 1.f) * 0.5f * 511.f;
                int ix = min(max((int)floorf(px), 0), 510);
                int iy = min(max((int)floorf(py), 0), 510);
                int il = min(max((int)floorf(pl), 0), 510);
                float wx = px - ix, wy = py - iy, wl = pl - il;
                const __half* pb = g_planesTh + ((long)((i_of*GRIDSZ + iy)*GRIDSZ) + ix)*NC + cj;
                const __half* lb = g_linesTh + (i_of*GRIDSZ + il)*NC + cj;
                uint2 u00 = *(const uint2*)pb;
                uint2 u01 = *(const uint2*)(pb + NC);
                uint2 u10 = *(const uint2*)(pb + GRIDSZ*NC);
                uint2 u11 = *(const uint2*)(pb + GRIDSZ*NC + NC);
                uint2 ul0 = *(const uint2*)lb;
                uint2 ul1 = *(const uint2*)(lb + NC);
                float2 f00a = __half22float2(*(__half2*)&u00.x), f00b = __half22float2(*(__half2*)&u00.y);
                float2 f01a = __half22float2(*(__half2*)&u01.x), f01b = __half22float2(*(__half2*)&u01.y);
                float2 f10a = __half22float2(*(__half2*)&u10.x), f10b = __half22float2(*(__half2*)&u10.y);
                float2 f11a = __half22float2(*(__half2*)&u11.x), f11b = __half22float2(*(__half2*)&u11.y);
                float2 l0a  = __half22float2(*(__half2*)&ul0.x), l0b  = __half22float2(*(__half2*)&ul0.y);
                float2 l1a  = __half22float2(*(__half2*)&ul1.x), l1b  = __half22float2(*(__half2*)&ul1.y);
                float rx, ry, rz, rw;
                float fx0, fx1;
                fx0 = f00a.x + wx*(f01a.x - f00a.x); fx1 = f10a.x + wx*(f11a.x - f10a.x);
                rx = (fx0 + wy*(fx1 - fx0)) * (l0a.x + wl*(l1a.x - l0a.x));
                fx0 = f00a.y + wx*(f01a.y - f00a.y); fx1 = f10a.y + wx*(f11a.y - f10a.y);
                ry = (fx0 + wy*(fx1 - fx0)) * (l0a.y + wl*(l1a.y - l0a.y));
                fx0 = f00b.x + wx*(f01b.x - f00b.x); fx1 = f10b.x + wx*(f11b.x - f10b.x);
                rz = (fx0 + wy*(fx1 - fx0)) * (l0b.x + wl*(l1b.x - l0b.x));
                fx0 = f00b.y + wx*(f01b.y - f00b.y); fx1 = f10b.y + wx*(f11b.y - f10b.y);
                rw = (fx0 + wy*(fx1 - fx0)) * (l0b.y + wl*(l1b.y - l0b.y));
                *(__half2*)(rbase + fcol*2)     = __floats2half2_rn(rx, ry);
                *(__half2*)(rbase + fcol*2 + 4) = __floats2half2_rn(rz, rw);
            }

            float pv;
            if (lane < 3) pv = (lane == 0) ? xn0 : ((lane == 1) ? xn1 : xn2);
            else if (lane < 21) {
                int j = lane - 3, f = j / 6, rr = j - 6*f, d = rr % 3;
                float xv = ((d == 0) ? xn0 : ((d == 1) ? xn1 : xn2)) * (float)(1 << f);
                pv = (rr < 3) ? __sinf(xv) : __cosf(xv);
            } else pv = 0.f;
            if (pcol < K1PAD)
                *(__half*)(rbase + pcol*2) = __float2half_rn(pv);
        }
    }

    cp_wait0();
    __syncthreads();

    // ================= GEMM1: 8 warps = 2m(32 rows) x 4n(64 cols), ldmatrix =================
    const int mt = warp & 1;
    const int nq = warp >> 1;          // 0..3
    const int arow = mt * 32;

    const int lrow  = (lane & 7) + ((lane >> 3) & 1) * 8;
    const int koffb = (lane >> 4) * 16;

    const uint32_t aAddr1 = smem_u32 + BY_A1 + (uint32_t)(arow + lrow)*SA1_B + koffb;
    const uint32_t bAddr1 = smem_u32 + BY_W1 + (uint32_t)(nq*64 + lrow)*SA1_B + koffb;
    const uint32_t aT1 = smem_u32 + BY_A1 + (uint32_t)(arow + lrow)*SA1_B + 256;
    const uint32_t bT1 = smem_u32 + BY_W1 + (uint32_t)(nq*64 + lrow)*SA1_B + 256;

    float acc[2][8][4];
    #pragma unroll
    for (int i = 0; i < 2; i++)
        #pragma unroll
        for (int j = 0; j < 8; j++)
            #pragma unroll
            for (int q = 0; q < 4; q++) acc[i][j][q] = 0.f;

    #pragma unroll
    for (int ks = 0; ks < 8; ks++) {
        unsigned a0, a1, a2, a3, a4, a5, a6, a7;
        ldsm_x4(a0, a1, a2, a3, aAddr1 + ks*32);
        ldsm_x4(a4, a5, a6, a7, aAddr1 + 16*SA1_B + ks*32);
        #pragma unroll
        for (int p = 0; p < 4; p++) {
            unsigned b0, b1, b2, b3;
            ldsm_x4(b0, b1, b2, b3, bAddr1 + (uint32_t)p*16*SA1_B + ks*32);
            mma_f16_k16(acc[0][2*p],   a0, a1, a2, a3, b0, b2);
            mma_f16_k16(acc[0][2*p+1], a0, a1, a2, a3, b1, b3);
            mma_f16_k16(acc[1][2*p],   a4, a5, a6, a7, b0, b2);
            mma_f16_k16(acc[1][2*p+1], a4, a5, a6, a7, b1, b3);
        }
    }
    {   // k8 tail: k = 128..135
        unsigned a0, a1, a4, a5;
        ldsm_x2(a0, a1, aT1);
        ldsm_x2(a4, a5, aT1 + 16*SA1_B);
        #pragma unroll
        for (int p = 0; p < 4; p++) {
            unsigned b0, b1;
            ldsm_x2(b0, b1, bT1 + (uint32_t)p*16*SA1_B);
            mma_f16_k8(acc[0][2*p],   a0, a1, b0);
            mma_f16_k8(acc[0][2*p+1], a0, a1, b1);
            mma_f16_k8(acc[1][2*p],   a4, a5, b0);
            mma_f16_k8(acc[1][2*p+1], a4, a5, b1);
        }
    }

    __syncthreads();   // all W1/A1 reads done

    // stage W2 image (144 x 528 B = 4752 x 16B)
    for (int idx = tid; idx < 4752; idx += NTHREADS)
        cp16(smem_u32 + BY_W2 + (uint32_t)idx*16u, (const char*)g_W2h + idx*16);
    cp_commit();

    // epilogue 1: bias + softplus -> fp16 A2 (stride 528B)
    #pragma unroll
    for (int mf = 0; mf < 2; mf++) {
        #pragma unroll
        for (int nf = 0; nf < 8; nf++) {
            int col = nq*64 + nf*8 + 2*t;
            float bb0 = b1s[col], bb1 = b1s[col+1];
            int row0 = arow + mf*16 + g;
            float r0 = softplus100(acc[mf][nf][0] + bb0);
            float r1 = softplus100(acc[mf][nf][1] + bb1);
            float r2 = softplus100(acc[mf][nf][2] + bb0);
            float r3 = softplus100(acc[mf][nf][3] + bb1);
            *(__half2*)(smem + BY_A2 + row0*SA2_B + col*2)     = __floats2half2_rn(r0, r1);
            *(__half2*)(smem + BY_A2 + (row0+8)*SA2_B + col*2) = __floats2half2_rn(r2, r3);
        }
    }

    cp_wait0();
    __syncthreads();

    // ================= GEMM2: 8 warps = 4m(16 rows) x 2n(72 cols), ldmatrix =================
    const int mt2 = warp & 3;
    const int nh2 = warp >> 2;         // 0..1
    const int arow2 = mt2 * 16;

    const uint32_t aAddr2 = smem_u32 + BY_A2 + (uint32_t)(arow2 + lrow)*SA2_B + koffb;
    const uint32_t bAddr2 = smem_u32 + BY_W2 + (uint32_t)(nh2*72 + lrow)*SA2_B + koffb;
    const uint32_t bAddr2e = smem_u32 + BY_W2 + (uint32_t)(nh2*72 + 64 + (lane & 7))*SA2_B
                           + ((lane >> 3) & 1) * 16;

    float acc2[9][4];
    #pragma unroll
    for (int j = 0; j < 9; j++)
        #pragma unroll
        for (int q = 0; q < 4; q++) acc2[j][q] = 0.f;

    #pragma unroll
    for (int ks = 0; ks < 16; ks++) {
        unsigned a0, a1, a2, a3;
        ldsm_x4(a0, a1, a2, a3, aAddr2 + ks*32);
        #pragma unroll
        for (int p = 0; p < 4; p++) {
            unsigned b0, b1, b2, b3;
            ldsm_x4(b0, b1, b2, b3, bAddr2 + (uint32_t)p*16*SA2_B + ks*32);
            mma_f16_k16(acc2[2*p],   a0, a1, a2, a3, b0, b2);
            mma_f16_k16(acc2[2*p+1], a0, a1, a2, a3, b1, b3);
        }
        {
            unsigned b0, b1;
            ldsm_x2(b0, b1, bAddr2e + ks*32);
            mma_f16_k16(acc2[8], a0, a1, a2, a3, b0, b1);
        }
    }

    // epilogue 2: bias + streaming store
    #pragma unroll
    for (int nf = 0; nf < 9; nf++) {
        int col = nh2*72 + nf*8 + 2*t;
        float o0 = acc2[nf][0] + b2s[col];
        float o1 = acc2[nf][1] + b2s[col+1];
        float o2 = acc2[nf][2] + b2s[col];
        float o3 = acc2[nf][3] + b2s[col+1];
        int r0 = (pbase + arow2 + g) * NOUT;
        int r1 = r0 + 8*NOUT;
        if (col < NOUT)     { __stcs(&out[r0 + col], o0);     __stcs(&out[r1 + col], o2); }
        if (col + 1 < NOUT) { __stcs(&out[r0 + col + 1], o1); __stcs(&out[r1 + col + 1], o3); }
    }
}

extern "C" void kernel_launch(void* const* d_in, const int* in_sizes, int n_in,
                              void* d_out, int out_size) {
    const float* xyz    = (const float*)d_in[0];
    const float* planes = (const float*)d_in[1];
    const float* lines  = (const float*)d_in[2];
    const float* W1     = (const float*)d_in[3];
    const float* b1     = (const float*)d_in[4];
    const float* W2     = (const float*)d_in[5];
    const float* b2     = (const float*)d_in[6];
    float* out = (float*)d_out;

    static bool attr_set = false;
    if (!attr_set) {
        cudaFuncSetAttribute(tensosdf_main,
                             cudaFuncAttributeMaxDynamicSharedMemorySize, SMEM_BYTES);
        attr_set = true;
    }

    transpose_planes<<<3072, 256>>>(planes);
    transpose_lines<<<6, 256>>>(lines);
    const int npack = 256*136 + N2PAD*264;
    pack_weights_kernel<<<(npack + 255) / 256, 256>>>(W1, W2);
    tensosdf_main<<<NPTS / TB, NTHREADS, SMEM_BYTES>>>(xyz, b1, b2, out);
}